// round 12
// baseline (speedup 1.0000x reference)
#include <cuda_runtime.h>

// Problem constants (static per reference)
#define NIMG 8
#define CINC 64
#define HH   112
#define WW   112
#define NP   (HH*WW)      // 12544 pixels/patches per image
#define NP4  (NP/4)       // 3136 float4 groups per image
#define COUTC 64
#define DD   576          // CIN*K*K
#define MEM  1025

// Scratch (device globals — no allocation allowed)
__device__ float d_S[NIMG*NP];                 // per-pixel channel sums
__device__ int   d_bins[NIMG*NP];              // bin per patch
__device__ int   d_first[NIMG*MEM];            // first-occurring patch idx per bin
__device__ float d_rep4[NIMG*(COUTC/4)*MEM*4]; // reps, quad layout: [n][c/4][bin][c%4]
__device__ float d_Wt[DD*COUTC];               // transposed weight: Wt[d*64 + c]
__device__ int   d_live[NIMG*MEM];             // compacted list of populated (n*MEM+b)
__device__ int   d_nlive;                      // count of populated bins

// K1: per-pixel channel sum (1 px/thread, MLP-rich) + init first table +
// weight transpose + live-count reset. Per-pixel FP order: sequential c=0..63,
// single accumulator — bit-identical to all validated rounds.
__global__ void k_prep(const float* __restrict__ fmap,
                       const float* __restrict__ weight) {
    int tid   = blockIdx.x * blockDim.x + threadIdx.x;   // [0, NIMG*NP)
    int total = gridDim.x * blockDim.x;

    if (tid == 0) d_nlive = 0;

    for (int i = tid; i < NIMG*MEM; i += total) d_first[i] = NP;

    for (int i = tid; i < COUTC*DD; i += total) {
        int c = i / DD, d = i - c*DD;
        d_Wt[d*COUTC + c] = weight[i];
    }

    int n = tid / NP, p = tid - n*NP;
    const float* base = fmap + (size_t)n * CINC * NP + p;
    float s = 0.f;
    #pragma unroll 16
    for (int c = 0; c < CINC; c++) s += base[c * NP];
    d_S[tid] = s;
}

// K2: 3x3 box sum (zero-padded) -> quantized bin -> scatter-min first.
// The unique thread that observes the pristine NP value appends the bin to
// the live list (exactly one winner per bin).
__global__ void k_bin() {
    int tid = blockIdx.x * blockDim.x + threadIdx.x;     // [0, NIMG*NP)
    int n = tid / NP, p = tid - n*NP;
    int h = p / WW, w = p - h*WW;
    const float* S = d_S + n*NP;

    float sum = 0.f;
    #pragma unroll
    for (int dy = -1; dy <= 1; dy++) {
        int y = h + dy;
        if (y < 0 || y >= HH) continue;
        const float* Sy = S + y*WW;
        if (w > 0)      sum += Sy[w - 1];
        sum += Sy[w];
        if (w < WW - 1) sum += Sy[w + 1];
    }

    float m = sum / (float)DD;
    int s = (int)(m * 100.0f);             // trunc toward zero == astype(int32)
    int b = s + 512;
    b = b < 0 ? 0 : (b > MEM-1 ? MEM-1 : b);
    d_bins[tid] = b;

    int pair = n*MEM + b;
    int old = atomicMin(&d_first[pair], p);
    if (old == NP) {
        int idx = atomicAdd(&d_nlive, 1);
        d_live[idx] = pair;
    }
}

// K3: representative GEMVs over the COMPACTED live list. Fixed 296-block grid
// strides the ~280 entries; 512 threads = 64 channels x 8 d-groups of 72.
__global__ void __launch_bounds__(512) k_rep(const float* __restrict__ fmap,
                                             const float* __restrict__ bias) {
    __shared__ float sh[DD];
    __shared__ float red[512];
    int t = threadIdx.x;
    int nlive = *(volatile int*)&d_nlive;

    for (int i = blockIdx.x; i < nlive; i += gridDim.x) {
        int pair = d_live[i];
        int n = pair / MEM, b = pair - n*MEM;
        int p = d_first[pair];
        int h = p / WW, w = p - h*WW;

        __syncthreads();                    // protect sh/red reuse across iterations
        for (int d = t; d < DD; d += 512) {
            int cin = d / 9, r = d - cin*9;
            int kh = r / 3, kw = r - kh*3;
            int y = h + kh - 1, x = w + kw - 1;
            float v = 0.f;
            if (y >= 0 && y < HH && x >= 0 && x < WW)
                v = fmap[(((size_t)n*CINC + cin)*HH + y)*WW + x];
            sh[d] = v;
        }
        __syncthreads();

        int c = t & 63;            // channel (lane-contiguous -> coalesced Wt loads)
        int g = t >> 6;            // d-group 0..7
        float acc = 0.f;
        int d0 = g * 72;
        #pragma unroll 8
        for (int d = d0; d < d0 + 72; d++)
            acc = fmaf(sh[d], d_Wt[d*COUTC + c], acc);
        red[t] = acc;
        __syncthreads();

        if (t < COUTC) {
            float r = bias[t];
            #pragma unroll
            for (int g2 = 0; g2 < 8; g2++) r += red[t + g2*64];
            // quad layout: [n][c/4][bin][c%4]
            d_rep4[(((size_t)n*(COUTC/4) + (t >> 2))*MEM + b)*4 + (t & 3)] = r;
        }
    }
}

// K4: gather + write with the rep row staged in SHARED memory.
// One block per (n, cq): stage rep4[n][cq][0..1024] (16.4 KB) into smem with
// one coalesced pass, then every gather is an LDS.128 (divergent addresses are
// native to smem; duplicated bins broadcast). Bins loads and output stores are
// fully coalesced; ~6-7 independent q-iterations per thread give MLP.
__global__ void __launch_bounds__(512) k_out(float* __restrict__ out) {
    __shared__ float4 srep[MEM];

    int cq = blockIdx.x;                   // 0..15
    int n  = blockIdx.y;                   // 0..7
    int t  = threadIdx.x;

    const float4* rt = (const float4*)d_rep4 + ((size_t)n*(COUTC/4) + cq)*MEM;
    for (int i = t; i < MEM; i += 512) srep[i] = rt[i];
    __syncthreads();

    const int4* bp = (const int4*)d_bins + n*NP4;
    int cbase = cq * 4;
    float4* obase = (float4*)out + ((size_t)n*COUTC + cbase)*NP4;

    for (int q = t; q < NP4; q += 512) {
        int4 b4 = bp[q];
        float4 v0 = srep[b4.x];
        float4 v1 = srep[b4.y];
        float4 v2 = srep[b4.z];
        float4 v3 = srep[b4.w];
        float4* ob = obase + q;
        ob[0*NP4] = make_float4(v0.x, v1.x, v2.x, v3.x);
        ob[1*NP4] = make_float4(v0.y, v1.y, v2.y, v3.y);
        ob[2*NP4] = make_float4(v0.z, v1.z, v2.z, v3.z);
        ob[3*NP4] = make_float4(v0.w, v1.w, v2.w, v3.w);
    }
}

extern "C" void kernel_launch(void* const* d_in, const int* in_sizes, int n_in,
                              void* d_out, int out_size) {
    const float* fmap   = (const float*)d_in[0];
    const float* weight = (const float*)d_in[1];
    const float* bias   = (const float*)d_in[2];
    float* out = (float*)d_out;

    (void)in_sizes; (void)n_in; (void)out_size;

    k_prep<<<(NIMG*NP + 255)/256, 256>>>(fmap, weight);    // 392 blocks
    k_bin <<<(NIMG*NP + 255)/256, 256>>>();                // 392 blocks
    k_rep <<<296, 512>>>(fmap, bias);                      // strides live list
    dim3 outGrid(COUTC/4, NIMG);                           // 16 x 8 = 128 blocks
    k_out <<<outGrid, 512>>>(out);
}

// round 14
// speedup vs baseline: 1.0625x; 1.0625x over previous
#include <cuda_runtime.h>

// Problem constants (static per reference)
#define NIMG 8
#define CINC 64
#define HH   112
#define WW   112
#define NP   (HH*WW)      // 12544 pixels/patches per image
#define NP4  (NP/4)       // 3136 float4 groups per image
#define COUTC 64
#define DD   576          // CIN*K*K
#define MEM  1025
#define QCHUNK 4          // q-range split for k_out
#define QLEN (NP4/QCHUNK) // 784 q-groups per block

// Scratch (device globals — no allocation allowed)
__device__ float d_S[NIMG*NP];                 // per-pixel channel sums
__device__ int   d_bins[NIMG*NP];              // bin per patch
__device__ int   d_first[NIMG*MEM];            // first-occurring patch idx per bin
__device__ float d_rep4[NIMG*(COUTC/4)*MEM*4]; // reps, quad layout: [n][c/4][bin][c%4]
__device__ float d_Wt[DD*COUTC];               // transposed weight: Wt[d*64 + c]
__device__ int   d_live[NIMG*MEM];             // compacted list of populated (n*MEM+b)
__device__ int   d_nlive;                      // count of populated bins

// K1: per-pixel channel sum (1 px/thread, MLP-rich) + init first table +
// weight transpose + live-count reset. Per-pixel FP order: sequential c=0..63,
// single accumulator — bit-identical to all validated rounds.
__global__ void k_prep(const float* __restrict__ fmap,
                       const float* __restrict__ weight) {
    int tid   = blockIdx.x * blockDim.x + threadIdx.x;   // [0, NIMG*NP)
    int total = gridDim.x * blockDim.x;

    if (tid == 0) d_nlive = 0;

    for (int i = tid; i < NIMG*MEM; i += total) d_first[i] = NP;

    for (int i = tid; i < COUTC*DD; i += total) {
        int c = i / DD, d = i - c*DD;
        d_Wt[d*COUTC + c] = weight[i];
    }

    int n = tid / NP, p = tid - n*NP;
    const float* base = fmap + (size_t)n * CINC * NP + p;
    float s = 0.f;
    #pragma unroll 16
    for (int c = 0; c < CINC; c++) s += base[c * NP];
    d_S[tid] = s;
}

// K2: 3x3 box sum (zero-padded) -> quantized bin -> scatter-min first.
// The unique thread that observes the pristine NP value appends the bin to
// the live list (exactly one winner per bin).
__global__ void k_bin() {
    int tid = blockIdx.x * blockDim.x + threadIdx.x;     // [0, NIMG*NP)
    int n = tid / NP, p = tid - n*NP;
    int h = p / WW, w = p - h*WW;
    const float* S = d_S + n*NP;

    float sum = 0.f;
    #pragma unroll
    for (int dy = -1; dy <= 1; dy++) {
        int y = h + dy;
        if (y < 0 || y >= HH) continue;
        const float* Sy = S + y*WW;
        if (w > 0)      sum += Sy[w - 1];
        sum += Sy[w];
        if (w < WW - 1) sum += Sy[w + 1];
    }

    float m = sum / (float)DD;
    int s = (int)(m * 100.0f);             // trunc toward zero == astype(int32)
    int b = s + 512;
    b = b < 0 ? 0 : (b > MEM-1 ? MEM-1 : b);
    d_bins[tid] = b;

    int pair = n*MEM + b;
    int old = atomicMin(&d_first[pair], p);
    if (old == NP) {
        int idx = atomicAdd(&d_nlive, 1);
        d_live[idx] = pair;
    }
}

// K3: representative GEMVs over the COMPACTED live list. Fixed 296-block grid
// strides the ~280 entries; 512 threads = 64 channels x 8 d-groups of 72.
__global__ void __launch_bounds__(512) k_rep(const float* __restrict__ fmap,
                                             const float* __restrict__ bias) {
    __shared__ float sh[DD];
    __shared__ float red[512];
    int t = threadIdx.x;
    int nlive = *(volatile int*)&d_nlive;

    for (int i = blockIdx.x; i < nlive; i += gridDim.x) {
        int pair = d_live[i];
        int n = pair / MEM, b = pair - n*MEM;
        int p = d_first[pair];
        int h = p / WW, w = p - h*WW;

        __syncthreads();                    // protect sh/red reuse across iterations
        for (int d = t; d < DD; d += 512) {
            int cin = d / 9, r = d - cin*9;
            int kh = r / 3, kw = r - kh*3;
            int y = h + kh - 1, x = w + kw - 1;
            float v = 0.f;
            if (y >= 0 && y < HH && x >= 0 && x < WW)
                v = fmap[(((size_t)n*CINC + cin)*HH + y)*WW + x];
            sh[d] = v;
        }
        __syncthreads();

        int c = t & 63;            // channel (lane-contiguous -> coalesced Wt loads)
        int g = t >> 6;            // d-group 0..7
        float acc = 0.f;
        int d0 = g * 72;
        #pragma unroll 8
        for (int d = d0; d < d0 + 72; d++)
            acc = fmaf(sh[d], d_Wt[d*COUTC + c], acc);
        red[t] = acc;
        __syncthreads();

        if (t < COUTC) {
            float r = bias[t];
            #pragma unroll
            for (int g2 = 0; g2 < 8; g2++) r += red[t + g2*64];
            // quad layout: [n][c/4][bin][c%4]
            d_rep4[(((size_t)n*(COUTC/4) + (t >> 2))*MEM + b)*4 + (t & 3)] = r;
        }
    }
}

// K4: gather + write with the rep row staged in SHARED memory, high occupancy.
// Grid (cq=16, n=8, qchunk=4) = 512 blocks x 256 threads. Each block stages
// rep4[n][cq][*] (16.4 KB) into smem (coalesced), then handles 784 q-groups:
// coalesced int4 bins load -> 4 LDS.128 gathers -> 4 coalesced STG.128.
__global__ void __launch_bounds__(256) k_out(float* __restrict__ out) {
    __shared__ float4 srep[MEM];

    int cq = blockIdx.x;                   // 0..15
    int n  = blockIdx.y;                   // 0..7
    int qc = blockIdx.z;                   // 0..QCHUNK-1
    int t  = threadIdx.x;

    const float4* rt = (const float4*)d_rep4 + ((size_t)n*(COUTC/4) + cq)*MEM;
    #pragma unroll
    for (int i = t; i < MEM; i += 256) srep[i] = rt[i];
    __syncthreads();

    const int4* bp = (const int4*)d_bins + n*NP4;
    int cbase = cq * 4;
    float4* obase = (float4*)out + ((size_t)n*COUTC + cbase)*NP4;
    int q0 = qc * QLEN;

    #pragma unroll
    for (int j = 0; j < QLEN/256 + 1; j++) {
        int q = q0 + j*256 + t;
        if (q >= q0 + QLEN) break;
        int4 b4 = bp[q];
        float4 v0 = srep[b4.x];
        float4 v1 = srep[b4.y];
        float4 v2 = srep[b4.z];
        float4 v3 = srep[b4.w];
        float4* ob = obase + q;
        ob[0*NP4] = make_float4(v0.x, v1.x, v2.x, v3.x);
        ob[1*NP4] = make_float4(v0.y, v1.y, v2.y, v3.y);
        ob[2*NP4] = make_float4(v0.z, v1.z, v2.z, v3.z);
        ob[3*NP4] = make_float4(v0.w, v1.w, v2.w, v3.w);
    }
}

extern "C" void kernel_launch(void* const* d_in, const int* in_sizes, int n_in,
                              void* d_out, int out_size) {
    const float* fmap   = (const float*)d_in[0];
    const float* weight = (const float*)d_in[1];
    const float* bias   = (const float*)d_in[2];
    float* out = (float*)d_out;

    (void)in_sizes; (void)n_in; (void)out_size;

    k_prep<<<(NIMG*NP + 255)/256, 256>>>(fmap, weight);    // 392 blocks
    k_bin <<<(NIMG*NP + 255)/256, 256>>>();                // 392 blocks
    k_rep <<<296, 512>>>(fmap, bias);                      // strides live list
    dim3 outGrid(COUTC/4, NIMG, QCHUNK);                   // 512 blocks
    k_out <<<outGrid, 256>>>(out);
}